// round 12
// baseline (speedup 1.0000x reference)
#include <cuda_runtime.h>
#include <cstdint>

// 3D spatial correlation sampler, patch=7, dil=1, k=1, s=1, pad=0
// in1,in2: [B=2, C=32, D=32, H=32, W=32] fp32
// out: [B, 7, 7, 7, D, H, W] fp32
//
// INVERTED decomposition: block = (b, hq, z-plane). The in2 slab for plane z
// (all 32 channels, zero-padded halo) is staged ONCE and kept resident; the
// block then loops over all valid (d, od) pairs with d+od-3 == z (4..7 pairs),
// staging only the small in1(d) tile per pair (8-channel chunks, double-
// buffered cp.async). Slab staging traffic drops 7x vs one-block-per-od.
// 96 invalid (d,od) combos -> trivial zero-store tail blocks (grid 256+96).
// Inner math: pair-aligned fma.rn.f32x2 (R7), conflict-free pitches 36/44.

#define BB 2
#define CC 32
#define DD 32
#define HH 32
#define WW 32
#define PP 7
#define TH 8
#define NTHREADS 224
#define CCHUNK 8
#define NCHUNK (CC / CCHUNK)     // 4
#define NWORK 256                // b(2) x hq(4) x z(32)

#define IN1_PITCH 36                               // step mod 32 = 4 -> conflict-free
#define IN1C_SZ (CCHUNK * TH * IN1_PITCH)          // 2304 floats per buf
#define SLAB_ROWS (TH + 6)                         // 14
#define SLAB_PITCH 44                              // step mod 32 = 12 -> conflict-free
#define SLAB_CSTRIDE (SLAB_ROWS * SLAB_PITCH)      // 616
#define SLAB_SZ (CC * SLAB_CSTRIDE)                // 19712 floats (all 32 c)
#define SMEM_FLOATS (SLAB_SZ + 2 * IN1C_SZ)        // 24320 floats = 97280 B

typedef unsigned long long u64;

__device__ __forceinline__ void cp_async16(uint32_t dst, const void* src, int src_bytes) {
    asm volatile("cp.async.cg.shared.global [%0], [%1], 16, %2;\n"
                 :: "r"(dst), "l"(src), "r"(src_bytes));
}
__device__ __forceinline__ void ffma2(u64& acc, u64 a, u64 b) {
    asm("fma.rn.f32x2 %0, %1, %2, %0;" : "+l"(acc) : "l"(a), "l"(b));
}
// O = (hi32(lo_src), lo32(hi_src))
__device__ __forceinline__ u64 mix_hi_lo(u64 lo_src, u64 hi_src) {
    uint32_t a0, a1, b0, b1;
    asm("mov.b64 {%0,%1}, %2;" : "=r"(a0), "=r"(a1) : "l"(lo_src));
    asm("mov.b64 {%0,%1}, %2;" : "=r"(b0), "=r"(b1) : "l"(hi_src));
    u64 r;
    asm("mov.b64 %0, {%1,%2};" : "=l"(r) : "r"(a1), "r"(b0));
    return r;
}

__global__ __launch_bounds__(NTHREADS, 2)
void corr3d_kernel(const float* __restrict__ in1,
                   const float* __restrict__ in2,
                   float* __restrict__ out)
{
    extern __shared__ float sm[];   // [slab 19712 | in1 buf0 2304 | in1 buf1 2304]

    const int bx   = blockIdx.x;
    const int t    = threadIdx.x;
    const int lane = t & 31;
    const int oh   = t >> 5;        // warp id = oh
    const int hl   = lane & 7;
    const int wi   = lane >> 3;
    const int w0   = wi * 8;

    if (bx >= NWORK) {
        // ---- trivial tail block: one invalid (b,hq,od,d), store zeros ----
        int u = bx - NWORK;                 // 0..95
        int g = u / 12;
        int r = u - g * 12;
        int od = 0, d = 0;
        #pragma unroll
        for (int o = 0; o < PP; o++) {
            int cnt = (o < 3) ? (3 - o) : (o - 3);
            if (r < cnt) { od = o; d = (o < 3) ? r : (35 - o + r); break; }
            r -= cnt;
        }
        const int hq = g & 3, b = g >> 2, h0 = hq * TH;
        size_t obase = (size_t)(((b * PP + od) * PP + oh) * PP) * (DD * HH * WW)
                     + (size_t)d * (HH * WW) + (h0 + hl) * WW + w0;
        const ulonglong2 z2 = make_ulonglong2(0ull, 0ull);
        #pragma unroll
        for (int pw = 0; pw < PP; pw++) {
            float* o = out + obase + (size_t)pw * (DD * HH * WW);
            *(ulonglong2*)(o)     = z2;
            *(ulonglong2*)(o + 4) = z2;
        }
        return;
    }

    // ---- work block: (b, hq, z) ----
    const int z  = bx & 31;
    const int g  = bx >> 5;
    const int hq = g & 3;
    const int b  = g >> 2;
    const int h0 = hq * TH;

    const int odlo = (z > 28) ? (z - 28) : 0;     // d = z+3-od in [0,31]
    const int odhi = (z < 3) ? (z + 3) : 6;
    const int npairs = odhi - odlo + 1;           // 4..7

    const float* in1b = in1 + (size_t)(b * CC) * (DD * HH * WW);
    const float* in2g = in2 + ((size_t)(b * CC) * DD + z) * (HH * WW);
    const uint32_t smem_u32 = (uint32_t)__cvta_generic_to_shared(sm);
    const uint32_t in1buf_u32 = smem_u32 + SLAB_SZ * 4u;

    // stage one 8-channel in1 chunk of plane d into buffer buf
    auto stage_in1 = [&](int dd, int chunk, int buf) {
        const float* g1 = in1b + (size_t)(chunk * CCHUNK) * (DD * HH * WW)
                               + (size_t)dd * (HH * WW);
        uint32_t dstb = in1buf_u32 + (uint32_t)(buf * IN1C_SZ) * 4u;
        #pragma unroll
        for (int i = 0; i < 3; i++) {
            int slot = i * NTHREADS + t;            // valid < 512
            if (slot < CCHUNK * TH * 8) {
                int c   = slot >> 6;
                int rem = slot & 63;
                int hh  = rem >> 3;
                int w4  = (rem & 7) * 4;
                cp_async16(dstb + (uint32_t)(c * (TH * IN1_PITCH)
                                             + hh * IN1_PITCH + w4) * 4u,
                           g1 + (size_t)c * (DD * HH * WW) + (h0 + hh) * WW + w4,
                           16);
            }
        }
        asm volatile("cp.async.commit_group;\n" ::);
    };

    // ---- prologue: stage full slab (32 c) + in1 chunk 0 of first pair ----
    #pragma unroll
    for (int i = 0; i < 20; i++) {
        int slot = i * NTHREADS + t;                // 0..4479
        int c    = slot / 140;
        int rem  = slot - c * 140;
        int r    = rem / 10;
        int s4   = rem - r * 10;
        int hg   = h0 + r - 3;
        bool v   = (s4 >= 1) && (s4 <= 8) && (hg >= 0) && (hg < HH);
        const float* src = v ? (in2g + (size_t)c * (DD * HH * WW)
                                     + hg * WW + (s4 - 1) * 4)
                             : in2g;        // clamped dummy, zfilled
        cp_async16(smem_u32 + (uint32_t)(c * SLAB_CSTRIDE
                                         + r * SLAB_PITCH + s4 * 4) * 4u,
                   src, v ? 16 : 0);
    }
    stage_in1(z + 3 - odlo, 0, 0);   // commits slab + first in1 chunk
    asm volatile("cp.async.wait_group 0;\n" ::);
    __syncthreads();

    int q = 0;                        // global chunk counter (buffer parity)
    for (int p = 0; p < npairs; p++) {
        const int od = odlo + p;
        const int d  = z + 3 - od;

        u64 acc2[PP][4];
        #pragma unroll
        for (int pw = 0; pw < PP; pw++)
            #pragma unroll
            for (int j = 0; j < 4; j++) acc2[pw][j] = 0ull;

        #pragma unroll
        for (int ch = 0; ch < NCHUNK; ch++) {
            const bool more = (ch < NCHUNK - 1) || (p + 1 < npairs);
            if (more) {
                int nd  = (ch < NCHUNK - 1) ? d : (d - 1);   // next pair: od+1 -> d-1
                int nch = (ch < NCHUNK - 1) ? (ch + 1) : 0;
                stage_in1(nd, nch, (q + 1) & 1);
            }

            const float* ap = sm + SLAB_SZ + (q & 1) * IN1C_SZ
                                 + hl * IN1_PITCH + w0;
            const float* bp = sm + (ch * CCHUNK) * SLAB_CSTRIDE
                                 + (hl + oh) * SLAB_PITCH + w0;

            #pragma unroll
            for (int c = 0; c < CCHUNK; c++) {
                ulonglong2 a01 = *(const ulonglong2*)(ap);      // av[0..3]
                ulonglong2 a23 = *(const ulonglong2*)(ap + 4);  // av[4..7]
                ulonglong2 e0  = *(const ulonglong2*)(bp);      // bb[0..3]
                ulonglong2 e1  = *(const ulonglong2*)(bp + 4);  // bb[4..7]
                ulonglong2 e2  = *(const ulonglong2*)(bp + 8);  // bb[8..11]
                ulonglong2 e3  = *(const ulonglong2*)(bp + 12); // bb[12..15]

                u64 A[4] = {a01.x, a01.y, a23.x, a23.y};
                u64 E[8] = {e0.x, e0.y, e1.x, e1.y, e2.x, e2.y, e3.x, e3.y};
                u64 O[7];                       // O[m] = (bb[2m+1], bb[2m+2])
                #pragma unroll
                for (int m = 0; m < 7; m++) O[m] = mix_hi_lo(E[m], E[m + 1]);

                // B pair start k = pw+1+2j; even k -> E[k/2], odd -> O[k/2]
                #pragma unroll
                for (int pw = 0; pw < PP; pw++)
                    #pragma unroll
                    for (int j = 0; j < 4; j++) {
                        const int k = pw + 1 + 2 * j;
                        ffma2(acc2[pw][j], A[j], (k & 1) ? O[k >> 1] : E[k >> 1]);
                    }

                ap += TH * IN1_PITCH;
                bp += SLAB_CSTRIDE;
            }

            if (more) {
                asm volatile("cp.async.wait_group 0;\n" ::);
                __syncthreads();   // next in1 chunk landed; buf reuse safe
            }
            q++;
        }

        // ---- store this (d, od) pair ----
        size_t obase = (size_t)(((b * PP + od) * PP + oh) * PP) * (DD * HH * WW)
                     + (size_t)d * (HH * WW) + (h0 + hl) * WW + w0;
        #pragma unroll
        for (int pw = 0; pw < PP; pw++) {
            float* o = out + obase + (size_t)pw * (DD * HH * WW);
            *(ulonglong2*)(o)     = make_ulonglong2(acc2[pw][0], acc2[pw][1]);
            *(ulonglong2*)(o + 4) = make_ulonglong2(acc2[pw][2], acc2[pw][3]);
        }
    }
}

extern "C" void kernel_launch(void* const* d_in, const int* in_sizes, int n_in,
                              void* d_out, int out_size)
{
    const float* in1 = (const float*)d_in[0];
    const float* in2 = (const float*)d_in[1];
    float* out = (float*)d_out;

    cudaFuncSetAttribute(corr3d_kernel,
                         cudaFuncAttributeMaxDynamicSharedMemorySize,
                         SMEM_FLOATS * sizeof(float));

    dim3 grid(NWORK + 96);   // 256 work (b,hq,z) + 96 zero-tail blocks
    dim3 block(NTHREADS);
    corr3d_kernel<<<grid, block, SMEM_FLOATS * sizeof(float)>>>(in1, in2, out);
}